// round 6
// baseline (speedup 1.0000x reference)
#include <cuda_runtime.h>

// Problem constants
#define CC   64          // channels (CIN == COUT)
#define SS   128         // H == W
#define P    16384       // SS*SS pixels
#define NB   2           // batch
#define FFT_SMEM (2*128*129*4)   // 132096 bytes: SoA re/im, pitch 129

// ---------------- device scratch (static __device__, no allocations) ----------------
__device__ float  g_Q    [NB*CC*P];   // Q, later reused as t2 = r2*out2 - ft
__device__ float  g_Kc   [NB*CC*P];
__device__ float  g_Vc   [NB*CC*P];
__device__ float  g_out  [NB*CC*P];
__device__ float2 g_F    [NB*P];      // fft2(out[:,32]) * 1/128
__device__ float  g_wsumR[CC*P];      // sum_i weights1_real[c,i,:,:]
__device__ float  g_wsumI[CC*P];
__device__ float  g_M    [CC*CC];
__device__ float  g_bias [CC];
__device__ float  g_part [128];

// ---------------- kernel 1: collapse conv chain to M, bias ----------------
__global__ void precompute_M(const float* __restrict__ w0,  const float* __restrict__ w0b,
                             const float* __restrict__ cv,  const float* __restrict__ cvb,
                             const float* __restrict__ cv1, const float* __restrict__ cv1b) {
    __shared__ float T[CC*CC];
    __shared__ float tb[CC];
    int tid = threadIdx.x;
    for (int idx = tid; idx < CC*CC; idx += 256) {
        int o = idx >> 6, c = idx & 63;
        float s = 0.f;
        #pragma unroll 8
        for (int k = 0; k < CC; k++) s += w0[o*CC + k] * cv[k*CC + c];
        T[idx] = s;
    }
    if (tid < CC) {
        float s = 0.f;
        for (int j = 0; j < CC; j++) s += w0[tid*CC + j] * cvb[j];
        tb[tid] = s + w0b[tid];
    }
    __syncthreads();
    for (int idx = tid; idx < CC*CC; idx += 256) {
        int o = idx >> 6, c = idx & 63;
        float s = 0.f;
        #pragma unroll 8
        for (int k = 0; k < CC; k++) s += cv1[o*CC + k] * T[k*CC + c];
        g_M[idx] = s;
    }
    if (tid < CC) {
        float s = 0.f;
        for (int k = 0; k < CC; k++) s += cv1[tid*CC + k] * tb[k];
        g_bias[tid] = s + cv1b[tid];
    }
}

// ---------------- kernel 2: Q/K/V 1x1 convs (tiled SGEMM) ----------------
// grid (128 pixel-tiles, NB), block 256, dyn smem 81920
__global__ void qkv_kernel(const float* __restrict__ fs,
                           const float* __restrict__ wq,
                           const float* __restrict__ wk,
                           const float* __restrict__ wv) {
    extern __shared__ float sm[];
    float* sw = sm;            // 3 * 64 * 64 (transposed: [m][k][o])
    float* sf = sm + 12288;    // 64 * 128
    int tid = threadIdx.x;
    int b   = blockIdx.y;
    int p0  = blockIdx.x * 128;

    const float* wmats[3] = {wq, wk, wv};
    #pragma unroll
    for (int m = 0; m < 3; m++) {
        const float* w = wmats[m];
        for (int idx = tid; idx < 4096; idx += 256) {
            int o = idx >> 6, k = idx & 63;
            sw[m*4096 + k*64 + o] = w[idx];
        }
    }
    for (int idx = tid; idx < 8192; idx += 256) {
        int c = idx >> 7, pp = idx & 127;
        sf[c*128 + pp] = fs[((b*CC + c) << 14) + p0 + pp];
    }
    __syncthreads();

    int c0  = (tid >> 4) * 4;
    int pp0 = (tid & 15) * 8;

    #pragma unroll
    for (int m = 0; m < 3; m++) {
        float acc[4][8];
        #pragma unroll
        for (int i = 0; i < 4; i++)
            #pragma unroll
            for (int j = 0; j < 8; j++) acc[i][j] = 0.f;

        #pragma unroll 4
        for (int k = 0; k < 64; k++) {
            float4 w4 = *reinterpret_cast<const float4*>(&sw[m*4096 + k*64 + c0]);
            float4 fa = *reinterpret_cast<const float4*>(&sf[k*128 + pp0]);
            float4 fb = *reinterpret_cast<const float4*>(&sf[k*128 + pp0 + 4]);
            float wv4[4] = {w4.x, w4.y, w4.z, w4.w};
            float fv[8]  = {fa.x, fa.y, fa.z, fa.w, fb.x, fb.y, fb.z, fb.w};
            #pragma unroll
            for (int i = 0; i < 4; i++)
                #pragma unroll
                for (int j = 0; j < 8; j++)
                    acc[i][j] += wv4[i] * fv[j];
        }
        float* dst = (m == 0) ? g_Q : ((m == 1) ? g_Kc : g_Vc);
        #pragma unroll
        for (int i = 0; i < 4; i++) {
            float* dp = dst + ((b*CC + c0 + i) << 14) + p0 + pp0;
            *reinterpret_cast<float4*>(dp)     = make_float4(acc[i][0], acc[i][1], acc[i][2], acc[i][3]);
            *reinterpret_cast<float4*>(dp + 4) = make_float4(acc[i][4], acc[i][5], acc[i][6], acc[i][7]);
        }
    }
}

// ---------------- kernel 3: 9-tap per-channel softmax attention ----------------
// grid 8192, block 256
__global__ void attn_kernel(const float* __restrict__ relh,
                            const float* __restrict__ relw) {
    int idx = blockIdx.x * 256 + threadIdx.x;
    int p  = idx & (P - 1);
    int bc = idx >> 14;
    int c  = bc & 63;
    int h  = p >> 7, w = p & 127;

    float q = g_Q[idx];
    float bias[9];
    if (c < 32) {
        float b0 = relh[c*3 + 0], b1 = relh[c*3 + 1], b2 = relh[c*3 + 2];
        bias[0] = bias[1] = bias[2] = b0;
        bias[3] = bias[4] = bias[5] = b1;
        bias[6] = bias[7] = bias[8] = b2;
    } else {
        float b0 = relw[(c-32)*3 + 0], b1 = relw[(c-32)*3 + 1], b2 = relw[(c-32)*3 + 2];
        bias[0] = bias[3] = bias[6] = b0;
        bias[1] = bias[4] = bias[7] = b1;
        bias[2] = bias[5] = bias[8] = b2;
    }
    const float* Kb = g_Kc + (bc << 14);
    const float* Vb = g_Vc + (bc << 14);

    float l[9], v[9];
    float mx = -1e30f;
    #pragma unroll
    for (int t = 0; t < 9; t++) {
        int dh = t / 3 - 1, dw = t % 3 - 1;
        int h2 = h + dh, w2 = w + dw;
        bool in = ((unsigned)h2 < 128u) && ((unsigned)w2 < 128u);
        float kk = in ? Kb[h2*128 + w2] : 0.f;
        float vv = in ? Vb[h2*128 + w2] : 0.f;
        kk += bias[t];
        l[t] = q * kk;
        v[t] = vv;
        mx = fmaxf(mx, l[t]);
    }
    float se = 0.f, acc = 0.f;
    #pragma unroll
    for (int t = 0; t < 9; t++) {
        float e = __expf(l[t] - mx);
        se  += e;
        acc += e * v[t];
    }
    g_out[idx] = acc / se;
}

// ---------------- warp-level 128-pt DIT FFT over shared memory ----------------
// Input must be in bit-reversed order. stride = smem element stride.
__device__ __forceinline__ void fft128(float* re, float* im, int lane, int stride,
                                       const float2* TW) {
    #pragma unroll
    for (int s = 1; s <= 7; s++) {
        int hf = 1 << (s - 1);
        __syncwarp();
        #pragma unroll
        for (int e = 0; e < 2; e++) {
            int bf = lane + 32*e;
            int j  = bf & (hf - 1);
            int i0 = ((bf >> (s - 1)) << s) + j;
            int i1 = i0 + hf;
            float2 w = TW[j << (7 - s)];
            int a0 = i0*stride, a1 = i1*stride;
            float ur = re[a0], ui = im[a0];
            float vr = re[a1], vi = im[a1];
            float tr = w.x*vr - w.y*vi;
            float ti = w.x*vi + w.y*vr;
            re[a0] = ur + tr; im[a0] = ui + ti;
            re[a1] = ur - tr; im[a1] = ui - ti;
        }
    }
    __syncwarp();
}

// ---------------- kernel 4: fused forward 2D FFT of out[:,32,:,:] ----------------
// grid NB, block 512, dyn smem FFT_SMEM
__global__ void fwd_fft_kernel() {
    extern __shared__ float sm[];
    float* Sre = sm;
    float* Sim = sm + 128*129;
    __shared__ float2 TW[64];
    int tid  = threadIdx.x;
    int wid  = tid >> 5;
    int lane = tid & 31;
    int b    = blockIdx.x;

    if (tid < 64) {
        float cs, sn;
        sincosf(-6.28318530717958647692f * (float)tid / 128.f, &cs, &sn);
        TW[tid] = make_float2(cs, sn);
    }
    const float* src = g_out + (b*CC + 32)*P;
    for (int idx = tid; idx < 16384; idx += 512) {
        int r = idx >> 7, j = idx & 127;
        int jr = __brev((unsigned)j) >> 25;
        Sre[r*129 + jr] = src[idx];
        Sim[r*129 + jr] = 0.f;
    }
    __syncthreads();

    // row pass (along w)
    #pragma unroll
    for (int t = 0; t < 8; t++) {
        int r = wid*8 + t;
        fft128(Sre + r*129, Sim + r*129, lane, 1, TW);
    }
    __syncthreads();

    // column pass (along h): bit-reverse column in registers, then DIT
    #pragma unroll
    for (int t = 0; t < 8; t++) {
        int v = wid*8 + t;
        float vr[4], vi[4];
        #pragma unroll
        for (int e = 0; e < 4; e++) {
            int j = lane + 32*e;
            vr[e] = Sre[j*129 + v];
            vi[e] = Sim[j*129 + v];
        }
        __syncwarp();
        #pragma unroll
        for (int e = 0; e < 4; e++) {
            int j  = lane + 32*e;
            int jr = __brev((unsigned)j) >> 25;
            Sre[jr*129 + v] = vr[e];
            Sim[jr*129 + v] = vi[e];
        }
        fft128(Sre + v, Sim + v, lane, 129, TW);
    }
    __syncthreads();

    const float sc = 1.f/128.f;   // ortho fft2
    for (int idx = tid; idx < 16384; idx += 512) {
        int u = idx >> 7, v = idx & 127;
        g_F[b*P + idx] = make_float2(Sre[u*129 + v]*sc, Sim[u*129 + v]*sc);
    }
}

// ---------------- kernel 5: weights1 reduction (the 512MB HBM stream) ----------------
// grid (16, 32), block 256; c = c0 + blockIdx.y
__global__ void wsum_kernel(const float* __restrict__ wr, const float* __restrict__ wi,
                            int c0) {
    int c  = c0 + blockIdx.y;
    int t4 = blockIdx.x * 256 + threadIdx.x;       // float4 index in [0,4096)
    const float4* pr = reinterpret_cast<const float4*>(wr + (long)c*CC*P) + t4;
    const float4* pi = reinterpret_cast<const float4*>(wi + (long)c*CC*P) + t4;

    float4 ar = make_float4(0,0,0,0), ai = make_float4(0,0,0,0);
    #pragma unroll 8
    for (int i = 0; i < 64; i++) {
        float4 r = pr[i*4096];
        float4 m = pi[i*4096];
        ar.x += r.x; ar.y += r.y; ar.z += r.z; ar.w += r.w;
        ai.x += m.x; ai.y += m.y; ai.z += m.z; ai.w += m.w;
    }
    reinterpret_cast<float4*>(g_wsumR)[c*4096 + t4] = ar;
    reinterpret_cast<float4*>(g_wsumI)[c*4096 + t4] = ai;
}

// ---------------- kernel 6: t2 = r2*(M@out + bias) - ft (transposed) -> g_Q ------
// grid 256 (= NB * 128 tiles), block 256, dyn smem 82432
__global__ void pre_final_kernel(const float* __restrict__ ft,
                                 const float* __restrict__ rate2) {
    extern __shared__ float sm[];
    float* sOut = sm;            // 64 * 128 = 8192
    float* sFt  = sm + 8192;     // 128 * 65 = 8320 (padded)
    float* sMT  = sm + 16512;    // 64 * 64  = 4096 (transposed [k][o])
    int tid = threadIdx.x;
    int b   = blockIdx.x >> 7;
    int p0  = (blockIdx.x & 127) * 128;

    for (int idx = tid; idx < 8192; idx += 256) {
        int c = idx >> 7, pp = idx & 127;
        sOut[idx] = g_out[((b*CC + c) << 14) + p0 + pp];
    }
    for (int idx = tid; idx < 8192; idx += 256) {
        int pp = idx >> 6, c = idx & 63;
        sFt[pp*65 + c] = ft[((long)(b*P + p0 + pp))*64 + c];
    }
    for (int idx = tid; idx < 4096; idx += 256) {
        int o = idx >> 6, k = idx & 63;
        sMT[k*64 + o] = g_M[idx];
    }
    __syncthreads();

    int c0  = (tid >> 4) * 4;
    int pp0 = (tid & 15) * 8;

    float acc[4][8];
    #pragma unroll
    for (int i = 0; i < 4; i++) {
        float bb = g_bias[c0 + i];
        #pragma unroll
        for (int j = 0; j < 8; j++) acc[i][j] = bb;
    }
    #pragma unroll 4
    for (int k = 0; k < 64; k++) {
        float4 m4 = *reinterpret_cast<const float4*>(&sMT[k*64 + c0]);
        float4 fa = *reinterpret_cast<const float4*>(&sOut[k*128 + pp0]);
        float4 fb = *reinterpret_cast<const float4*>(&sOut[k*128 + pp0 + 4]);
        float mv[4] = {m4.x, m4.y, m4.z, m4.w};
        float fv[8] = {fa.x, fa.y, fa.z, fa.w, fb.x, fb.y, fb.z, fb.w};
        #pragma unroll
        for (int i = 0; i < 4; i++)
            #pragma unroll
            for (int j = 0; j < 8; j++)
                acc[i][j] += mv[i] * fv[j];
    }

    float r2 = rate2[0];
    #pragma unroll
    for (int i = 0; i < 4; i++) {
        int c = c0 + i;
        float o8[8];
        #pragma unroll
        for (int j = 0; j < 8; j++)
            o8[j] = r2 * acc[i][j] - sFt[(pp0 + j)*65 + c];
        float* dp = g_Q + ((b*CC + c) << 14) + p0 + pp0;
        *reinterpret_cast<float4*>(dp)     = make_float4(o8[0], o8[1], o8[2], o8[3]);
        *reinterpret_cast<float4*>(dp + 4) = make_float4(o8[4], o8[5], o8[6], o8[7]);
    }
}

// ---------------- kernel 7: freq-mul + fused 2D inverse FFT + loss ----------------
// grid 64 (= NB * 32 channels of this half), block 512, dyn smem FFT_SMEM
__global__ void ifft_loss_kernel(const float* __restrict__ rate1, int c0) {
    extern __shared__ float sm[];
    float* Sre = sm;
    float* Sim = sm + 128*129;
    __shared__ float2 TW[64];
    __shared__ float red[512];
    int tid  = threadIdx.x;
    int wid  = tid >> 5;
    int lane = tid & 31;
    int b    = blockIdx.x & 1;
    int c    = c0 + (blockIdx.x >> 1);

    if (tid < 64) {
        float cs, sn;
        sincosf(6.28318530717958647692f * (float)tid / 128.f, &cs, &sn);
        TW[tid] = make_float2(cs, sn);
    }
    const float2* Fp = g_F + b*P;
    const float*  wr = g_wsumR + c*P;
    const float*  wi = g_wsumI + c*P;
    for (int idx = tid; idx < 16384; idx += 512) {
        int u = idx >> 7, v = idx & 127;
        float2 F = Fp[idx];
        float sr = wr[idx], si = wi[idx];
        int vr_ = __brev((unsigned)v) >> 25;
        Sre[u*129 + vr_] = sr*F.x - si*F.y;
        Sim[u*129 + vr_] = sr*F.y + si*F.x;
    }
    __syncthreads();

    // inverse along v (rows)
    #pragma unroll
    for (int t = 0; t < 8; t++) {
        int r = wid*8 + t;
        fft128(Sre + r*129, Sim + r*129, lane, 1, TW);
    }
    __syncthreads();

    // inverse along u (columns)
    #pragma unroll
    for (int t = 0; t < 8; t++) {
        int v = wid*8 + t;
        float vr[4], vi[4];
        #pragma unroll
        for (int e = 0; e < 4; e++) {
            int j = lane + 32*e;
            vr[e] = Sre[j*129 + v];
            vi[e] = Sim[j*129 + v];
        }
        __syncwarp();
        #pragma unroll
        for (int e = 0; e < 4; e++) {
            int j  = lane + 32*e;
            int jr = __brev((unsigned)j) >> 25;
            Sre[jr*129 + v] = vr[e];
            Sim[jr*129 + v] = vi[e];
        }
        fft128(Sre + v, Sim + v, lane, 129, TW);
    }
    __syncthreads();

    // loss: (r1 * out1 + t2)^2 ; out1 = Re * (1/128) (ortho ifft2)
    float r1 = rate1[0] * (1.f/128.f);
    const float* t2 = g_Q + ((b*CC + c) << 14);
    float local = 0.f;
    for (int idx = tid; idx < 16384; idx += 512) {
        int u = idx >> 7, v = idx & 127;
        float val = r1 * Sre[u*129 + v] + t2[idx];
        local += val * val;
    }
    red[tid] = local;
    __syncthreads();
    for (int s = 256; s > 0; s >>= 1) {
        if (tid < s) red[tid] += red[tid + s];
        __syncthreads();
    }
    if (tid == 0) g_part[(c0 ? 64 : 0) + blockIdx.x] = red[0];
}

__global__ void reduce_kernel(float* __restrict__ out) {
    __shared__ float s[128];
    s[threadIdx.x] = g_part[threadIdx.x];
    __syncthreads();
    for (int st = 64; st > 0; st >>= 1) {
        if (threadIdx.x < st) s[threadIdx.x] += s[threadIdx.x + st];
        __syncthreads();
    }
    if (threadIdx.x == 0) out[0] = s[0] / 2097152.0f;  // mean over 2*64*128*128
}

// ---------------- host ----------------
extern "C" void kernel_launch(void* const* d_in, const int* in_sizes, int n_in,
                              void* d_out, int out_size) {
    const float* fs    = (const float*)d_in[0];
    const float* ft    = (const float*)d_in[1];
    const float* w_q   = (const float*)d_in[2];
    const float* w_k   = (const float*)d_in[3];
    const float* w_v   = (const float*)d_in[4];
    const float* rel_h = (const float*)d_in[5];
    const float* rel_w = (const float*)d_in[6];
    const float* w1r   = (const float*)d_in[7];
    const float* w1i   = (const float*)d_in[8];
    const float* w0w   = (const float*)d_in[9];
    const float* w0b   = (const float*)d_in[10];
    const float* cvw   = (const float*)d_in[11];
    const float* cvb   = (const float*)d_in[12];
    const float* cv1w  = (const float*)d_in[13];
    const float* cv1b  = (const float*)d_in[14];
    const float* rate1 = (const float*)d_in[15];
    const float* rate2 = (const float*)d_in[16];

    // one-time host-side resources (created on the first, non-captured call)
    static bool s_init = false;
    static cudaStream_t s2;
    static cudaEvent_t evFork, evJ1, evJ2;
    if (!s_init) {
        cudaStreamCreateWithFlags(&s2, cudaStreamNonBlocking);
        cudaEventCreateWithFlags(&evFork, cudaEventDisableTiming);
        cudaEventCreateWithFlags(&evJ1,   cudaEventDisableTiming);
        cudaEventCreateWithFlags(&evJ2,   cudaEventDisableTiming);
        cudaFuncSetAttribute(qkv_kernel,       cudaFuncAttributeMaxDynamicSharedMemorySize, 81920);
        cudaFuncSetAttribute(pre_final_kernel, cudaFuncAttributeMaxDynamicSharedMemorySize, 82432);
        cudaFuncSetAttribute(fwd_fft_kernel,   cudaFuncAttributeMaxDynamicSharedMemorySize, FFT_SMEM);
        cudaFuncSetAttribute(ifft_loss_kernel, cudaFuncAttributeMaxDynamicSharedMemorySize, FFT_SMEM);
        s_init = true;
    }

    // ---- fork: the 512MB weights reduction runs concurrently on s2 ----
    cudaEventRecord(evFork, 0);
    cudaStreamWaitEvent(s2, evFork, 0);
    wsum_kernel<<<dim3(16, 32), 256, 0, s2>>>(w1r, w1i, 0);
    cudaEventRecord(evJ1, s2);
    wsum_kernel<<<dim3(16, 32), 256, 0, s2>>>(w1r, w1i, 32);
    cudaEventRecord(evJ2, s2);

    // ---- main chain (hidden under wsum) ----
    precompute_M<<<1, 256>>>(w0w, w0b, cvw, cvb, cv1w, cv1b);
    qkv_kernel<<<dim3(128, 2), 256, 81920>>>(fs, w_q, w_k, w_v);
    attn_kernel<<<8192, 256>>>(rel_h, rel_w);
    fwd_fft_kernel<<<NB, 512, FFT_SMEM>>>();
    pre_final_kernel<<<256, 256, 82432>>>(ft, rate2);

    // ---- join + inverse FFT / loss (split by channel halves) ----
    cudaStreamWaitEvent(0, evJ1, 0);
    ifft_loss_kernel<<<64, 512, FFT_SMEM>>>(rate1, 0);
    cudaStreamWaitEvent(0, evJ2, 0);
    ifft_loss_kernel<<<64, 512, FFT_SMEM>>>(rate1, 32);
    reduce_kernel<<<1, 128>>>((float*)d_out);
}

// round 7
// speedup vs baseline: 1.1991x; 1.1991x over previous
#include <cuda_runtime.h>

// Problem constants
#define CC   64          // channels (CIN == COUT)
#define SS   128         // H == W
#define P    16384       // SS*SS pixels
#define NB   2           // batch

// ---------------- device scratch (static __device__, no allocations) ----------------
__device__ float  g_Q    [NB*CC*P];   // Q, later reused as t2 = r2*out2 - ft
__device__ float  g_Kc   [NB*CC*P];
__device__ float  g_Vc   [NB*CC*P];
__device__ float  g_out  [NB*CC*P];
__device__ float2 g_F    [NB*P];      // ortho fft2(out[:,32])
__device__ float2 g_bufA [NB*CC*P];   // FFT ping buffer
__device__ float  g_wsumR[CC*P];
__device__ float  g_wsumI[CC*P];
__device__ float  g_M    [CC*CC];
__device__ float  g_bias [CC];
__device__ float  g_part [2048];

// ---------------- kernel 1: collapse conv chain to M, bias ----------------
__global__ void precompute_M(const float* __restrict__ w0,  const float* __restrict__ w0b,
                             const float* __restrict__ cv,  const float* __restrict__ cvb,
                             const float* __restrict__ cv1, const float* __restrict__ cv1b) {
    __shared__ float T[CC*CC];
    __shared__ float tb[CC];
    int tid = threadIdx.x;
    for (int idx = tid; idx < CC*CC; idx += 256) {
        int o = idx >> 6, c = idx & 63;
        float s = 0.f;
        #pragma unroll 8
        for (int k = 0; k < CC; k++) s += w0[o*CC + k] * cv[k*CC + c];
        T[idx] = s;
    }
    if (tid < CC) {
        float s = 0.f;
        for (int j = 0; j < CC; j++) s += w0[tid*CC + j] * cvb[j];
        tb[tid] = s + w0b[tid];
    }
    __syncthreads();
    for (int idx = tid; idx < CC*CC; idx += 256) {
        int o = idx >> 6, c = idx & 63;
        float s = 0.f;
        #pragma unroll 8
        for (int k = 0; k < CC; k++) s += cv1[o*CC + k] * T[k*CC + c];
        g_M[idx] = s;
    }
    if (tid < CC) {
        float s = 0.f;
        for (int k = 0; k < CC; k++) s += cv1[tid*CC + k] * tb[k];
        g_bias[tid] = s + cv1b[tid];
    }
}

// ---------------- kernel 2: Q/K/V 1x1 convs, one matrix per block (grid.z) ----------------
// grid (128 pixel-tiles, NB, 3), block 256, dyn smem 49152
__global__ void qkv_kernel(const float* __restrict__ fs,
                           const float* __restrict__ wq,
                           const float* __restrict__ wk,
                           const float* __restrict__ wv) {
    extern __shared__ float sm[];
    float* sw = sm;            // 64 * 64 (transposed: [k][o])
    float* sf = sm + 4096;     // 64 * 128
    int tid = threadIdx.x;
    int b   = blockIdx.y;
    int m   = blockIdx.z;
    int p0  = blockIdx.x * 128;

    const float* w = (m == 0) ? wq : ((m == 1) ? wk : wv);
    for (int idx = tid; idx < 4096; idx += 256) {
        int o = idx >> 6, k = idx & 63;
        sw[k*64 + o] = w[idx];
    }
    for (int idx = tid; idx < 8192; idx += 256) {
        int c = idx >> 7, pp = idx & 127;
        sf[c*128 + pp] = fs[((b*CC + c) << 14) + p0 + pp];
    }
    __syncthreads();

    int c0  = (tid >> 4) * 4;
    int pp0 = (tid & 15) * 8;

    float acc[4][8];
    #pragma unroll
    for (int i = 0; i < 4; i++)
        #pragma unroll
        for (int j = 0; j < 8; j++) acc[i][j] = 0.f;

    #pragma unroll 4
    for (int k = 0; k < 64; k++) {
        float4 w4 = *reinterpret_cast<const float4*>(&sw[k*64 + c0]);
        float4 fa = *reinterpret_cast<const float4*>(&sf[k*128 + pp0]);
        float4 fb = *reinterpret_cast<const float4*>(&sf[k*128 + pp0 + 4]);
        float wv4[4] = {w4.x, w4.y, w4.z, w4.w};
        float fv[8]  = {fa.x, fa.y, fa.z, fa.w, fb.x, fb.y, fb.z, fb.w};
        #pragma unroll
        for (int i = 0; i < 4; i++)
            #pragma unroll
            for (int j = 0; j < 8; j++)
                acc[i][j] += wv4[i] * fv[j];
    }
    float* dst = (m == 0) ? g_Q : ((m == 1) ? g_Kc : g_Vc);
    #pragma unroll
    for (int i = 0; i < 4; i++) {
        float* dp = dst + ((b*CC + c0 + i) << 14) + p0 + pp0;
        *reinterpret_cast<float4*>(dp)     = make_float4(acc[i][0], acc[i][1], acc[i][2], acc[i][3]);
        *reinterpret_cast<float4*>(dp + 4) = make_float4(acc[i][4], acc[i][5], acc[i][6], acc[i][7]);
    }
}

// ---------------- kernel 3: 9-tap per-channel softmax attention ----------------
// grid 8192, block 256
__global__ void attn_kernel(const float* __restrict__ relh,
                            const float* __restrict__ relw) {
    int idx = blockIdx.x * 256 + threadIdx.x;
    int p  = idx & (P - 1);
    int bc = idx >> 14;
    int c  = bc & 63;
    int h  = p >> 7, w = p & 127;

    float q = g_Q[idx];
    float bias[9];
    if (c < 32) {
        float b0 = relh[c*3 + 0], b1 = relh[c*3 + 1], b2 = relh[c*3 + 2];
        bias[0] = bias[1] = bias[2] = b0;
        bias[3] = bias[4] = bias[5] = b1;
        bias[6] = bias[7] = bias[8] = b2;
    } else {
        float b0 = relw[(c-32)*3 + 0], b1 = relw[(c-32)*3 + 1], b2 = relw[(c-32)*3 + 2];
        bias[0] = bias[3] = bias[6] = b0;
        bias[1] = bias[4] = bias[7] = b1;
        bias[2] = bias[5] = bias[8] = b2;
    }
    const float* Kb = g_Kc + (bc << 14);
    const float* Vb = g_Vc + (bc << 14);

    float l[9], v[9];
    float mx = -1e30f;
    #pragma unroll
    for (int t = 0; t < 9; t++) {
        int dh = t / 3 - 1, dw = t % 3 - 1;
        int h2 = h + dh, w2 = w + dw;
        bool in = ((unsigned)h2 < 128u) && ((unsigned)w2 < 128u);
        float kk = in ? Kb[h2*128 + w2] : 0.f;
        float vv = in ? Vb[h2*128 + w2] : 0.f;
        kk += bias[t];
        l[t] = q * kk;
        v[t] = vv;
        mx = fmaxf(mx, l[t]);
    }
    float se = 0.f, acc = 0.f;
    #pragma unroll
    for (int t = 0; t < 9; t++) {
        float e = __expf(l[t] - mx);
        se  += e;
        acc += e * v[t];
    }
    g_out[idx] = acc / se;
}

// ---------------- warp 128-pt DIT FFT over an smem row (stride 1), TW table ----------------
__device__ __forceinline__ void fft128_row(float2* S, int lane, const float2* TW) {
    #pragma unroll
    for (int s = 1; s <= 7; s++) {
        int hf = 1 << (s - 1);
        __syncwarp();
        #pragma unroll
        for (int e = 0; e < 2; e++) {
            int bf = lane + 32*e;
            int j  = bf & (hf - 1);
            int i0 = ((bf >> (s - 1)) << s) + j;
            int i1 = i0 + hf;
            float2 w = TW[j << (7 - s)];
            float2 u = S[i0], v = S[i1];
            float tr = w.x*v.x - w.y*v.y;
            float ti = w.x*v.y + w.y*v.x;
            S[i0] = make_float2(u.x + tr, u.y + ti);
            S[i1] = make_float2(u.x - tr, u.y - ti);
        }
    }
    __syncwarp();
}

// ---------------- forward FFT passes (2 transforms: out[:,32]) ----------------
// grid 32 (= 2 transforms * 16 row-blocks), block 256
__global__ void fwd_pass1() {
    __shared__ float2 S[8][128];
    __shared__ float2 TW[64];
    int tid  = threadIdx.x;
    int t    = blockIdx.x >> 4;
    int rb   = blockIdx.x & 15;
    int wid  = tid >> 5;
    int lane = tid & 31;
    int a    = rb*8 + wid;

    if (tid < 64) {
        float cs, sn;
        sincosf(-6.28318530717958647692f * (float)tid / 128.f, &cs, &sn);
        TW[tid] = make_float2(cs, sn);
    }
    __syncthreads();

    const float* p = g_out + (t*CC + 32)*P + a*128;
    #pragma unroll
    for (int e = 0; e < 4; e++) {
        int j = lane + e*32;
        int r = __brev((unsigned)j) >> 25;
        S[wid][r] = make_float2(p[j], 0.f);
    }
    fft128_row(S[wid], lane, TW);
    __syncthreads();

    #pragma unroll
    for (int it = 0; it < 4; it++) {
        int el = it*256 + tid;
        int j  = el >> 3, aa = el & 7;
        g_bufA[(long)t*P + j*128 + rb*8 + aa] = S[aa][j];   // transposed
    }
}

__global__ void fwd_pass2() {
    __shared__ float2 S[8][128];
    __shared__ float2 TW[64];
    int tid  = threadIdx.x;
    int t    = blockIdx.x >> 4;
    int rb   = blockIdx.x & 15;
    int wid  = tid >> 5;
    int lane = tid & 31;
    int a    = rb*8 + wid;

    if (tid < 64) {
        float cs, sn;
        sincosf(-6.28318530717958647692f * (float)tid / 128.f, &cs, &sn);
        TW[tid] = make_float2(cs, sn);
    }
    __syncthreads();

    const float2* p = g_bufA + (long)t*P + a*128;
    #pragma unroll
    for (int e = 0; e < 4; e++) {
        int j = lane + e*32;
        int r = __brev((unsigned)j) >> 25;
        S[wid][r] = p[j];
    }
    fft128_row(S[wid], lane, TW);
    __syncthreads();

    const float sc = 1.f/128.f;   // ortho fft2
    #pragma unroll
    for (int it = 0; it < 4; it++) {
        int el = it*256 + tid;
        int j  = el >> 3, aa = el & 7;
        float2 v = S[aa][j];
        g_F[(long)t*P + j*128 + rb*8 + aa] = make_float2(v.x*sc, v.y*sc);
    }
}

// ---------------- kernel 5: weights1 reduction (512MB HBM stream, high MLP) ----------------
// grid (32, 64), block 128
__global__ void __launch_bounds__(128) wsum_kernel(const float* __restrict__ wr,
                                                   const float* __restrict__ wi) {
    int c  = blockIdx.y;
    int t4 = blockIdx.x * 128 + threadIdx.x;       // float4 index in [0,4096)
    const float4* pr = reinterpret_cast<const float4*>(wr + (long)c*CC*P) + t4;
    const float4* pi = reinterpret_cast<const float4*>(wi + (long)c*CC*P) + t4;

    float4 ar = make_float4(0,0,0,0), ai = make_float4(0,0,0,0);
    #pragma unroll
    for (int o = 0; o < 8; o++) {
        float4 R[8], Mv[8];
        #pragma unroll
        for (int k = 0; k < 8; k++) R[k]  = pr[(o*8 + k)*4096];
        #pragma unroll
        for (int k = 0; k < 8; k++) Mv[k] = pi[(o*8 + k)*4096];
        #pragma unroll
        for (int k = 0; k < 8; k++) {
            ar.x += R[k].x;  ar.y += R[k].y;  ar.z += R[k].z;  ar.w += R[k].w;
            ai.x += Mv[k].x; ai.y += Mv[k].y; ai.z += Mv[k].z; ai.w += Mv[k].w;
        }
    }
    reinterpret_cast<float4*>(g_wsumR)[c*4096 + t4] = ar;
    reinterpret_cast<float4*>(g_wsumI)[c*4096 + t4] = ai;
}

// ---------------- kernel 6: t2 = r2*(M@out + bias) - ft (transposed) -> g_Q ------
// grid 256 (= NB * 128 tiles), block 256, dyn smem 82432
__global__ void pre_final_kernel(const float* __restrict__ ft,
                                 const float* __restrict__ rate2) {
    extern __shared__ float sm[];
    float* sOut = sm;            // 64 * 128 = 8192
    float* sFt  = sm + 8192;     // 128 * 65 = 8320 (padded)
    float* sMT  = sm + 16512;    // 64 * 64  = 4096 (transposed [k][o])
    int tid = threadIdx.x;
    int b   = blockIdx.x >> 7;
    int p0  = (blockIdx.x & 127) * 128;

    for (int idx = tid; idx < 8192; idx += 256) {
        int c = idx >> 7, pp = idx & 127;
        sOut[idx] = g_out[((b*CC + c) << 14) + p0 + pp];
    }
    for (int idx = tid; idx < 8192; idx += 256) {
        int pp = idx >> 6, c = idx & 63;
        sFt[pp*65 + c] = ft[((long)(b*P + p0 + pp))*64 + c];
    }
    for (int idx = tid; idx < 4096; idx += 256) {
        int o = idx >> 6, k = idx & 63;
        sMT[k*64 + o] = g_M[idx];
    }
    __syncthreads();

    int c0  = (tid >> 4) * 4;
    int pp0 = (tid & 15) * 8;

    float acc[4][8];
    #pragma unroll
    for (int i = 0; i < 4; i++) {
        float bb = g_bias[c0 + i];
        #pragma unroll
        for (int j = 0; j < 8; j++) acc[i][j] = bb;
    }
    #pragma unroll 4
    for (int k = 0; k < 64; k++) {
        float4 m4 = *reinterpret_cast<const float4*>(&sMT[k*64 + c0]);
        float4 fa = *reinterpret_cast<const float4*>(&sOut[k*128 + pp0]);
        float4 fb = *reinterpret_cast<const float4*>(&sOut[k*128 + pp0 + 4]);
        float mv[4] = {m4.x, m4.y, m4.z, m4.w};
        float fv[8] = {fa.x, fa.y, fa.z, fa.w, fb.x, fb.y, fb.z, fb.w};
        #pragma unroll
        for (int i = 0; i < 4; i++)
            #pragma unroll
            for (int j = 0; j < 8; j++)
                acc[i][j] += mv[i] * fv[j];
    }

    float r2 = rate2[0];
    #pragma unroll
    for (int i = 0; i < 4; i++) {
        int c = c0 + i;
        float o8[8];
        #pragma unroll
        for (int j = 0; j < 8; j++)
            o8[j] = r2 * acc[i][j] - sFt[(pp0 + j)*65 + c];
        float* dp = g_Q + ((b*CC + c) << 14) + p0 + pp0;
        *reinterpret_cast<float4*>(dp)     = make_float4(o8[0], o8[1], o8[2], o8[3]);
        *reinterpret_cast<float4*>(dp + 4) = make_float4(o8[4], o8[5], o8[6], o8[7]);
    }
}

// ---------------- inverse pass 1: freq-multiply + row FFT (128 transforms) ----------------
// grid 2048 (= 128 transforms * 16 row-blocks), block 256
__global__ void inv_pass1() {
    __shared__ float2 S[8][128];
    __shared__ float2 TW[64];
    int tid  = threadIdx.x;
    int t    = blockIdx.x >> 4;     // t = b*64 + c
    int rb   = blockIdx.x & 15;
    int wid  = tid >> 5;
    int lane = tid & 31;
    int b    = t >> 6;
    int c    = t & 63;
    int a    = rb*8 + wid;          // u row

    if (tid < 64) {
        float cs, sn;
        sincosf(6.28318530717958647692f * (float)tid / 128.f, &cs, &sn);
        TW[tid] = make_float2(cs, sn);
    }
    __syncthreads();

    const float2* Fp = g_F + b*P + a*128;
    const float*  wr = g_wsumR + c*P + a*128;
    const float*  wi = g_wsumI + c*P + a*128;
    #pragma unroll
    for (int e = 0; e < 4; e++) {
        int j = lane + e*32;
        int r = __brev((unsigned)j) >> 25;
        float2 F = Fp[j];
        float sr = wr[j], si = wi[j];
        S[wid][r] = make_float2(sr*F.x - si*F.y, sr*F.y + si*F.x);
    }
    fft128_row(S[wid], lane, TW);
    __syncthreads();

    #pragma unroll
    for (int it = 0; it < 4; it++) {
        int el = it*256 + tid;
        int j  = el >> 3, aa = el & 7;
        g_bufA[(long)t*P + j*128 + rb*8 + aa] = S[aa][j];   // transposed
    }
}

// ---------------- inverse pass 2 + fused loss ----------------
// grid 2048, block 256
__global__ void inv_pass2_loss(const float* __restrict__ rate1) {
    __shared__ float2 S[8][128];
    __shared__ float2 TW[64];
    __shared__ float red[256];
    int tid  = threadIdx.x;
    int t    = blockIdx.x >> 4;
    int rb   = blockIdx.x & 15;
    int wid  = tid >> 5;
    int lane = tid & 31;
    int a    = rb*8 + wid;          // v row

    if (tid < 64) {
        float cs, sn;
        sincosf(6.28318530717958647692f * (float)tid / 128.f, &cs, &sn);
        TW[tid] = make_float2(cs, sn);
    }
    __syncthreads();

    const float2* p = g_bufA + (long)t*P + a*128;
    #pragma unroll
    for (int e = 0; e < 4; e++) {
        int j = lane + e*32;
        int r = __brev((unsigned)j) >> 25;
        S[wid][r] = p[j];
    }
    fft128_row(S[wid], lane, TW);
    __syncthreads();

    // loss: (r1/128 * Re + t2)^2 over this block's 1024 output elements
    float r1s = rate1[0] * (1.f/128.f);
    const float* t2 = g_Q + (long)t*P;   // t = b*64+c matches (b*CC+c) layout
    float local = 0.f;
    #pragma unroll
    for (int it = 0; it < 4; it++) {
        int el = it*256 + tid;
        int j  = el >> 3, aa = el & 7;
        float val = r1s * S[aa][j].x + t2[j*128 + rb*8 + aa];
        local += val * val;
    }
    red[tid] = local;
    __syncthreads();
    for (int s = 128; s > 0; s >>= 1) {
        if (tid < s) red[tid] += red[tid + s];
        __syncthreads();
    }
    if (tid == 0) g_part[blockIdx.x] = red[0];
}

__global__ void reduce_kernel(float* __restrict__ out) {
    __shared__ float s[256];
    float v = 0.f;
    #pragma unroll
    for (int k = 0; k < 8; k++) v += g_part[threadIdx.x + k*256];
    s[threadIdx.x] = v;
    __syncthreads();
    for (int st = 128; st > 0; st >>= 1) {
        if (threadIdx.x < st) s[threadIdx.x] += s[threadIdx.x + st];
        __syncthreads();
    }
    if (threadIdx.x == 0) out[0] = s[0] / 2097152.0f;  // mean over 2*64*128*128
}

// ---------------- host ----------------
extern "C" void kernel_launch(void* const* d_in, const int* in_sizes, int n_in,
                              void* d_out, int out_size) {
    const float* fs    = (const float*)d_in[0];
    const float* ft    = (const float*)d_in[1];
    const float* w_q   = (const float*)d_in[2];
    const float* w_k   = (const float*)d_in[3];
    const float* w_v   = (const float*)d_in[4];
    const float* rel_h = (const float*)d_in[5];
    const float* rel_w = (const float*)d_in[6];
    const float* w1r   = (const float*)d_in[7];
    const float* w1i   = (const float*)d_in[8];
    const float* w0w   = (const float*)d_in[9];
    const float* w0b   = (const float*)d_in[10];
    const float* cvw   = (const float*)d_in[11];
    const float* cvb   = (const float*)d_in[12];
    const float* cv1w  = (const float*)d_in[13];
    const float* cv1b  = (const float*)d_in[14];
    const float* rate1 = (const float*)d_in[15];
    const float* rate2 = (const float*)d_in[16];

    static bool s_init = false;
    static cudaStream_t s2;
    static cudaEvent_t evFork, evJ;
    if (!s_init) {
        cudaStreamCreateWithFlags(&s2, cudaStreamNonBlocking);
        cudaEventCreateWithFlags(&evFork, cudaEventDisableTiming);
        cudaEventCreateWithFlags(&evJ,    cudaEventDisableTiming);
        cudaFuncSetAttribute(qkv_kernel,       cudaFuncAttributeMaxDynamicSharedMemorySize, 49152);
        cudaFuncSetAttribute(pre_final_kernel, cudaFuncAttributeMaxDynamicSharedMemorySize, 82432);
        s_init = true;
    }

    // ---- fork: the 512MB weights reduction runs concurrently on s2 ----
    cudaEventRecord(evFork, 0);
    cudaStreamWaitEvent(s2, evFork, 0);
    wsum_kernel<<<dim3(32, 64), 128, 0, s2>>>(w1r, w1i);
    cudaEventRecord(evJ, s2);

    // ---- main chain (hidden under wsum if the graph forks) ----
    precompute_M<<<1, 256>>>(w0w, w0b, cvw, cvb, cv1w, cv1b);
    qkv_kernel<<<dim3(128, 2, 3), 256, 49152>>>(fs, w_q, w_k, w_v);
    attn_kernel<<<8192, 256>>>(rel_h, rel_w);
    fwd_pass1<<<32, 256>>>();
    fwd_pass2<<<32, 256>>>();
    pre_final_kernel<<<256, 256, 82432>>>(ft, rate2);

    // ---- join + inverse FFT with fused freq-mul and loss ----
    cudaStreamWaitEvent(0, evJ, 0);
    inv_pass1<<<2048, 256>>>();
    inv_pass2_loss<<<2048, 256>>>(rate1);
    reduce_kernel<<<1, 256>>>((float*)d_out);
}

// round 8
// speedup vs baseline: 1.2904x; 1.0762x over previous
#include <cuda_runtime.h>

// Problem constants
#define CC   64          // channels (CIN == COUT)
#define SS   128         // H == W
#define P    16384       // SS*SS pixels
#define NB   2           // batch

// ---------------- device scratch (static __device__, no allocations) ----------------
__device__ float  g_Q    [NB*CC*P];   // Q, later reused as t2 = r2*out2 - ft
__device__ float  g_Kc   [NB*CC*P];
__device__ float  g_Vc   [NB*CC*P];
__device__ float  g_out  [NB*CC*P];
__device__ float2 g_F    [NB*P];      // ortho fft2(out[:,32])
__device__ float2 g_bufA [NB*CC*P];   // FFT ping buffer
__device__ float  g_M    [CC*CC];
__device__ float  g_bias [CC];
__device__ float  g_part [2048];

// ---------------- kernel 1: collapse conv chain to M, bias ----------------
__global__ void precompute_M(const float* __restrict__ w0,  const float* __restrict__ w0b,
                             const float* __restrict__ cv,  const float* __restrict__ cvb,
                             const float* __restrict__ cv1, const float* __restrict__ cv1b) {
    __shared__ float T[CC*CC];
    __shared__ float tb[CC];
    int tid = threadIdx.x;
    for (int idx = tid; idx < CC*CC; idx += 256) {
        int o = idx >> 6, c = idx & 63;
        float s = 0.f;
        #pragma unroll 8
        for (int k = 0; k < CC; k++) s += w0[o*CC + k] * cv[k*CC + c];
        T[idx] = s;
    }
    if (tid < CC) {
        float s = 0.f;
        for (int j = 0; j < CC; j++) s += w0[tid*CC + j] * cvb[j];
        tb[tid] = s + w0b[tid];
    }
    __syncthreads();
    for (int idx = tid; idx < CC*CC; idx += 256) {
        int o = idx >> 6, c = idx & 63;
        float s = 0.f;
        #pragma unroll 8
        for (int k = 0; k < CC; k++) s += cv1[o*CC + k] * T[k*CC + c];
        g_M[idx] = s;
    }
    if (tid < CC) {
        float s = 0.f;
        for (int k = 0; k < CC; k++) s += cv1[tid*CC + k] * tb[k];
        g_bias[tid] = s + cv1b[tid];
    }
}

// ---------------- kernel 2: Q/K/V 1x1 convs, one matrix per block (grid.z) ----------------
// grid (128 pixel-tiles, NB, 3), block 256, dyn smem 49152
__global__ void qkv_kernel(const float* __restrict__ fs,
                           const float* __restrict__ wq,
                           const float* __restrict__ wk,
                           const float* __restrict__ wv) {
    extern __shared__ float sm[];
    float* sw = sm;            // 64 * 64 (transposed: [k][o])
    float* sf = sm + 4096;     // 64 * 128
    int tid = threadIdx.x;
    int b   = blockIdx.y;
    int m   = blockIdx.z;
    int p0  = blockIdx.x * 128;

    const float* w = (m == 0) ? wq : ((m == 1) ? wk : wv);
    for (int idx = tid; idx < 4096; idx += 256) {
        int o = idx >> 6, k = idx & 63;
        sw[k*64 + o] = w[idx];
    }
    for (int idx = tid; idx < 8192; idx += 256) {
        int c = idx >> 7, pp = idx & 127;
        sf[c*128 + pp] = fs[((b*CC + c) << 14) + p0 + pp];
    }
    __syncthreads();

    int c0  = (tid >> 4) * 4;
    int pp0 = (tid & 15) * 8;

    float acc[4][8];
    #pragma unroll
    for (int i = 0; i < 4; i++)
        #pragma unroll
        for (int j = 0; j < 8; j++) acc[i][j] = 0.f;

    #pragma unroll 4
    for (int k = 0; k < 64; k++) {
        float4 w4 = *reinterpret_cast<const float4*>(&sw[k*64 + c0]);
        float4 fa = *reinterpret_cast<const float4*>(&sf[k*128 + pp0]);
        float4 fb = *reinterpret_cast<const float4*>(&sf[k*128 + pp0 + 4]);
        float wv4[4] = {w4.x, w4.y, w4.z, w4.w};
        float fv[8]  = {fa.x, fa.y, fa.z, fa.w, fb.x, fb.y, fb.z, fb.w};
        #pragma unroll
        for (int i = 0; i < 4; i++)
            #pragma unroll
            for (int j = 0; j < 8; j++)
                acc[i][j] += wv4[i] * fv[j];
    }
    float* dst = (m == 0) ? g_Q : ((m == 1) ? g_Kc : g_Vc);
    #pragma unroll
    for (int i = 0; i < 4; i++) {
        float* dp = dst + ((b*CC + c0 + i) << 14) + p0 + pp0;
        *reinterpret_cast<float4*>(dp)     = make_float4(acc[i][0], acc[i][1], acc[i][2], acc[i][3]);
        *reinterpret_cast<float4*>(dp + 4) = make_float4(acc[i][4], acc[i][5], acc[i][6], acc[i][7]);
    }
}

// ---------------- kernel 3: 9-tap per-channel softmax attention ----------------
// grid 8192, block 256
__global__ void attn_kernel(const float* __restrict__ relh,
                            const float* __restrict__ relw) {
    int idx = blockIdx.x * 256 + threadIdx.x;
    int p  = idx & (P - 1);
    int bc = idx >> 14;
    int c  = bc & 63;
    int h  = p >> 7, w = p & 127;

    float q = g_Q[idx];
    float bias[9];
    if (c < 32) {
        float b0 = relh[c*3 + 0], b1 = relh[c*3 + 1], b2 = relh[c*3 + 2];
        bias[0] = bias[1] = bias[2] = b0;
        bias[3] = bias[4] = bias[5] = b1;
        bias[6] = bias[7] = bias[8] = b2;
    } else {
        float b0 = relw[(c-32)*3 + 0], b1 = relw[(c-32)*3 + 1], b2 = relw[(c-32)*3 + 2];
        bias[0] = bias[3] = bias[6] = b0;
        bias[1] = bias[4] = bias[7] = b1;
        bias[2] = bias[5] = bias[8] = b2;
    }
    const float* Kb = g_Kc + (bc << 14);
    const float* Vb = g_Vc + (bc << 14);

    float l[9], v[9];
    float mx = -1e30f;
    #pragma unroll
    for (int t = 0; t < 9; t++) {
        int dh = t / 3 - 1, dw = t % 3 - 1;
        int h2 = h + dh, w2 = w + dw;
        bool in = ((unsigned)h2 < 128u) && ((unsigned)w2 < 128u);
        float kk = in ? Kb[h2*128 + w2] : 0.f;
        float vv = in ? Vb[h2*128 + w2] : 0.f;
        kk += bias[t];
        l[t] = q * kk;
        v[t] = vv;
        mx = fmaxf(mx, l[t]);
    }
    float se = 0.f, acc = 0.f;
    #pragma unroll
    for (int t = 0; t < 9; t++) {
        float e = __expf(l[t] - mx);
        se  += e;
        acc += e * v[t];
    }
    g_out[idx] = acc / se;
}

// ---------------- warp 128-pt DIT FFT over an smem row (stride 1), TW table ----------------
__device__ __forceinline__ void fft128_row(float2* S, int lane, const float2* TW) {
    #pragma unroll
    for (int s = 1; s <= 7; s++) {
        int hf = 1 << (s - 1);
        __syncwarp();
        #pragma unroll
        for (int e = 0; e < 2; e++) {
            int bf = lane + 32*e;
            int j  = bf & (hf - 1);
            int i0 = ((bf >> (s - 1)) << s) + j;
            int i1 = i0 + hf;
            float2 w = TW[j << (7 - s)];
            float2 u = S[i0], v = S[i1];
            float tr = w.x*v.x - w.y*v.y;
            float ti = w.x*v.y + w.y*v.x;
            S[i0] = make_float2(u.x + tr, u.y + ti);
            S[i1] = make_float2(u.x - tr, u.y - ti);
        }
    }
    __syncwarp();
}

// ---------------- forward FFT passes (2 transforms: out[:,32]) ----------------
// grid 32 (= 2 transforms * 16 row-blocks), block 256
__global__ void fwd_pass1() {
    __shared__ float2 S[8][128];
    __shared__ float2 TW[64];
    int tid  = threadIdx.x;
    int t    = blockIdx.x >> 4;
    int rb   = blockIdx.x & 15;
    int wid  = tid >> 5;
    int lane = tid & 31;
    int a    = rb*8 + wid;

    if (tid < 64) {
        float cs, sn;
        sincosf(-6.28318530717958647692f * (float)tid / 128.f, &cs, &sn);
        TW[tid] = make_float2(cs, sn);
    }
    __syncthreads();

    const float* p = g_out + (t*CC + 32)*P + a*128;
    #pragma unroll
    for (int e = 0; e < 4; e++) {
        int j = lane + e*32;
        int r = __brev((unsigned)j) >> 25;
        S[wid][r] = make_float2(p[j], 0.f);
    }
    fft128_row(S[wid], lane, TW);
    __syncthreads();

    #pragma unroll
    for (int it = 0; it < 4; it++) {
        int el = it*256 + tid;
        int j  = el >> 3, aa = el & 7;
        g_bufA[(long)t*P + j*128 + rb*8 + aa] = S[aa][j];   // transposed
    }
}

__global__ void fwd_pass2() {
    __shared__ float2 S[8][128];
    __shared__ float2 TW[64];
    int tid  = threadIdx.x;
    int t    = blockIdx.x >> 4;
    int rb   = blockIdx.x & 15;
    int wid  = tid >> 5;
    int lane = tid & 31;
    int a    = rb*8 + wid;

    if (tid < 64) {
        float cs, sn;
        sincosf(-6.28318530717958647692f * (float)tid / 128.f, &cs, &sn);
        TW[tid] = make_float2(cs, sn);
    }
    __syncthreads();

    const float2* p = g_bufA + (long)t*P + a*128;
    #pragma unroll
    for (int e = 0; e < 4; e++) {
        int j = lane + e*32;
        int r = __brev((unsigned)j) >> 25;
        S[wid][r] = p[j];
    }
    fft128_row(S[wid], lane, TW);
    __syncthreads();

    const float sc = 1.f/128.f;   // ortho fft2
    #pragma unroll
    for (int it = 0; it < 4; it++) {
        int el = it*256 + tid;
        int j  = el >> 3, aa = el & 7;
        float2 v = S[aa][j];
        g_F[(long)t*P + j*128 + rb*8 + aa] = make_float2(v.x*sc, v.y*sc);
    }
}

// ---------------- kernel 6: t2 = r2*(M@out + bias) - ft (transposed) -> g_Q ------
// grid 256 (= NB * 128 tiles), block 256, dyn smem 82432
__global__ void pre_final_kernel(const float* __restrict__ ft,
                                 const float* __restrict__ rate2) {
    extern __shared__ float sm[];
    float* sOut = sm;            // 64 * 128 = 8192
    float* sFt  = sm + 8192;     // 128 * 65 = 8320 (padded)
    float* sMT  = sm + 16512;    // 64 * 64  = 4096 (transposed [k][o])
    int tid = threadIdx.x;
    int b   = blockIdx.x >> 7;
    int p0  = (blockIdx.x & 127) * 128;

    for (int idx = tid; idx < 8192; idx += 256) {
        int c = idx >> 7, pp = idx & 127;
        sOut[idx] = g_out[((b*CC + c) << 14) + p0 + pp];
    }
    for (int idx = tid; idx < 8192; idx += 256) {
        int pp = idx >> 6, c = idx & 63;
        sFt[pp*65 + c] = ft[((long)(b*P + p0 + pp))*64 + c];
    }
    for (int idx = tid; idx < 4096; idx += 256) {
        int o = idx >> 6, k = idx & 63;
        sMT[k*64 + o] = g_M[idx];
    }
    __syncthreads();

    int c0  = (tid >> 4) * 4;
    int pp0 = (tid & 15) * 8;

    float acc[4][8];
    #pragma unroll
    for (int i = 0; i < 4; i++) {
        float bb = g_bias[c0 + i];
        #pragma unroll
        for (int j = 0; j < 8; j++) acc[i][j] = bb;
    }
    #pragma unroll 4
    for (int k = 0; k < 64; k++) {
        float4 m4 = *reinterpret_cast<const float4*>(&sMT[k*64 + c0]);
        float4 fa = *reinterpret_cast<const float4*>(&sOut[k*128 + pp0]);
        float4 fb = *reinterpret_cast<const float4*>(&sOut[k*128 + pp0 + 4]);
        float mv[4] = {m4.x, m4.y, m4.z, m4.w};
        float fv[8] = {fa.x, fa.y, fa.z, fa.w, fb.x, fb.y, fb.z, fb.w};
        #pragma unroll
        for (int i = 0; i < 4; i++)
            #pragma unroll
            for (int j = 0; j < 8; j++)
                acc[i][j] += mv[i] * fv[j];
    }

    float r2 = rate2[0];
    #pragma unroll
    for (int i = 0; i < 4; i++) {
        int c = c0 + i;
        float o8[8];
        #pragma unroll
        for (int j = 0; j < 8; j++)
            o8[j] = r2 * acc[i][j] - sFt[(pp0 + j)*65 + c];
        float* dp = g_Q + ((b*CC + c) << 14) + p0 + pp0;
        *reinterpret_cast<float4*>(dp)     = make_float4(o8[0], o8[1], o8[2], o8[3]);
        *reinterpret_cast<float4*>(dp + 4) = make_float4(o8[4], o8[5], o8[6], o8[7]);
    }
}

// ---------------- FUSED: weights1 i-sum (512MB stream) + freq-mul + row iFFT --------
// grid 1024 (= 64 channels * 16 u-blocks), block 256
// Each block: streams its 512KB slice of w1r/w1i (sum over i=0..63 for 1024 uv
// points), then does the complex multiply with g_F and the row-FFT for BOTH
// batch images, writing transposed to g_bufA. Weights are read exactly once,
// via __ldcs (streaming, no L2 pollution).
__global__ void __launch_bounds__(256) invA_kernel(const float* __restrict__ w1r,
                                                   const float* __restrict__ w1i) {
    __shared__ float  sR[1024], sI[1024];
    __shared__ float2 S[8][128];
    __shared__ float2 TW[64];
    int tid  = threadIdx.x;
    int c    = blockIdx.x >> 4;
    int rb   = blockIdx.x & 15;
    int wid  = tid >> 5;
    int lane = tid & 31;

    if (tid < 64) {
        float cs, sn;
        sincosf(6.28318530717958647692f * (float)tid / 128.f, &cs, &sn);
        TW[tid] = make_float2(cs, sn);
    }

    // ---- phase A: i-sum. thread owns 4 consecutive floats (one float4) of the
    //      1024-point uv chunk [rb*1024, rb*1024+1024). i stride = P floats = 4096 f4.
    const float4* pR = reinterpret_cast<const float4*>(w1r + (size_t)c*CC*P + rb*1024) + tid;
    const float4* pI = reinterpret_cast<const float4*>(w1i + (size_t)c*CC*P + rb*1024) + tid;

    float4 aR = make_float4(0,0,0,0), aI = make_float4(0,0,0,0);
    #pragma unroll
    for (int io = 0; io < 4; io++) {
        float4 R[16];
        #pragma unroll
        for (int j = 0; j < 16; j++) R[j] = __ldcs(&pR[(io*16 + j)*4096]);
        #pragma unroll
        for (int j = 0; j < 16; j++) {
            aR.x += R[j].x; aR.y += R[j].y; aR.z += R[j].z; aR.w += R[j].w;
        }
    }
    #pragma unroll
    for (int io = 0; io < 4; io++) {
        float4 Mv[16];
        #pragma unroll
        for (int j = 0; j < 16; j++) Mv[j] = __ldcs(&pI[(io*16 + j)*4096]);
        #pragma unroll
        for (int j = 0; j < 16; j++) {
            aI.x += Mv[j].x; aI.y += Mv[j].y; aI.z += Mv[j].z; aI.w += Mv[j].w;
        }
    }
    reinterpret_cast<float4*>(sR)[tid] = aR;
    reinterpret_cast<float4*>(sI)[tid] = aI;
    __syncthreads();

    // ---- phase B: per batch image: multiply by F, row FFT, transposed store ----
    #pragma unroll
    for (int b = 0; b < NB; b++) {
        const float2* Fp = g_F + b*P + (rb*8 + wid)*128;
        #pragma unroll
        for (int e = 0; e < 4; e++) {
            int j = lane + e*32;
            int r = __brev((unsigned)j) >> 25;
            float2 F  = Fp[j];
            float  sr = sR[wid*128 + j];
            float  si = sI[wid*128 + j];
            S[wid][r] = make_float2(sr*F.x - si*F.y, sr*F.y + si*F.x);
        }
        fft128_row(S[wid], lane, TW);
        __syncthreads();

        long t = (long)b*64 + c;
        #pragma unroll
        for (int it = 0; it < 4; it++) {
            int el = it*256 + tid;
            int j  = el >> 3, aa = el & 7;
            g_bufA[t*P + j*128 + rb*8 + aa] = S[aa][j];   // transposed
        }
        __syncthreads();
    }
}

// ---------------- inverse pass 2 + fused loss ----------------
// grid 2048, block 256
__global__ void inv_pass2_loss(const float* __restrict__ rate1) {
    __shared__ float2 S[8][128];
    __shared__ float2 TW[64];
    __shared__ float red[256];
    int tid  = threadIdx.x;
    int t    = blockIdx.x >> 4;
    int rb   = blockIdx.x & 15;
    int wid  = tid >> 5;
    int lane = tid & 31;
    int a    = rb*8 + wid;          // v row

    if (tid < 64) {
        float cs, sn;
        sincosf(6.28318530717958647692f * (float)tid / 128.f, &cs, &sn);
        TW[tid] = make_float2(cs, sn);
    }
    __syncthreads();

    const float2* p = g_bufA + (long)t*P + a*128;
    #pragma unroll
    for (int e = 0; e < 4; e++) {
        int j = lane + e*32;
        int r = __brev((unsigned)j) >> 25;
        S[wid][r] = p[j];
    }
    fft128_row(S[wid], lane, TW);
    __syncthreads();

    // loss: (r1/128 * Re + t2)^2 over this block's 1024 output elements
    float r1s = rate1[0] * (1.f/128.f);
    const float* t2 = g_Q + (long)t*P;   // t = b*64+c matches (b*CC+c) layout
    float local = 0.f;
    #pragma unroll
    for (int it = 0; it < 4; it++) {
        int el = it*256 + tid;
        int j  = el >> 3, aa = el & 7;
        float val = r1s * S[aa][j].x + t2[j*128 + rb*8 + aa];
        local += val * val;
    }
    red[tid] = local;
    __syncthreads();
    for (int s = 128; s > 0; s >>= 1) {
        if (tid < s) red[tid] += red[tid + s];
        __syncthreads();
    }
    if (tid == 0) g_part[blockIdx.x] = red[0];
}

__global__ void reduce_kernel(float* __restrict__ out) {
    __shared__ float s[256];
    float v = 0.f;
    #pragma unroll
    for (int k = 0; k < 8; k++) v += g_part[threadIdx.x + k*256];
    s[threadIdx.x] = v;
    __syncthreads();
    for (int st = 128; st > 0; st >>= 1) {
        if (threadIdx.x < st) s[threadIdx.x] += s[threadIdx.x + st];
        __syncthreads();
    }
    if (threadIdx.x == 0) out[0] = s[0] / 2097152.0f;  // mean over 2*64*128*128
}

// ---------------- host ----------------
extern "C" void kernel_launch(void* const* d_in, const int* in_sizes, int n_in,
                              void* d_out, int out_size) {
    const float* fs    = (const float*)d_in[0];
    const float* ft    = (const float*)d_in[1];
    const float* w_q   = (const float*)d_in[2];
    const float* w_k   = (const float*)d_in[3];
    const float* w_v   = (const float*)d_in[4];
    const float* rel_h = (const float*)d_in[5];
    const float* rel_w = (const float*)d_in[6];
    const float* w1r   = (const float*)d_in[7];
    const float* w1i   = (const float*)d_in[8];
    const float* w0w   = (const float*)d_in[9];
    const float* w0b   = (const float*)d_in[10];
    const float* cvw   = (const float*)d_in[11];
    const float* cvb   = (const float*)d_in[12];
    const float* cv1w  = (const float*)d_in[13];
    const float* cv1b  = (const float*)d_in[14];
    const float* rate1 = (const float*)d_in[15];
    const float* rate2 = (const float*)d_in[16];

    static bool s_init = false;
    if (!s_init) {
        cudaFuncSetAttribute(qkv_kernel,       cudaFuncAttributeMaxDynamicSharedMemorySize, 49152);
        cudaFuncSetAttribute(pre_final_kernel, cudaFuncAttributeMaxDynamicSharedMemorySize, 82432);
        s_init = true;
    }

    precompute_M<<<1, 256>>>(w0w, w0b, cvw, cvb, cv1w, cv1b);
    qkv_kernel<<<dim3(128, 2, 3), 256, 49152>>>(fs, w_q, w_k, w_v);
    attn_kernel<<<8192, 256>>>(rel_h, rel_w);
    fwd_pass1<<<32, 256>>>();
    fwd_pass2<<<32, 256>>>();
    pre_final_kernel<<<256, 256, 82432>>>(ft, rate2);
    invA_kernel<<<1024, 256>>>(w1r, w1i);        // the 512MB stream, fused
    inv_pass2_loss<<<2048, 256>>>(rate1);
    reduce_kernel<<<1, 256>>>((float*)d_out);
}